// round 16
// baseline (speedup 1.0000x reference)
#include <cuda_runtime.h>

#define SEQ      784
#define BATCH    512
#define NTHREADS 128
#define SPB      4                     // sequences per block = warps per block
#define EL       16                    // packed pairs per lane (covers 32 elems: (i, i+16))

typedef unsigned long long u64;

// ---- f32x2 packed helpers (sm_100+/sm_103a; FFMA2 reachable only via PTX) ----
__device__ __forceinline__ u64 pk(float lo, float hi) {
    u64 r; asm("mov.b64 %0, {%1, %2};" : "=l"(r) : "f"(lo), "f"(hi)); return r;
}
__device__ __forceinline__ void upk(u64 v, float& lo, float& hi) {
    asm("mov.b64 {%0, %1}, %2;" : "=f"(lo), "=f"(hi) : "l"(v));
}
__device__ __forceinline__ u64 fma2(u64 a, u64 b, u64 c) {
    u64 d; asm("fma.rn.f32x2 %0, %1, %2, %3;" : "=l"(d) : "l"(a), "l"(b), "l"(c)); return d;
}
__device__ __forceinline__ u64 mul2(u64 a, u64 b) {
    u64 d; asm("mul.rn.f32x2 %0, %1, %2;" : "=l"(d) : "l"(a), "l"(b)); return d;
}

// Quad tanh from pre-scaled args (xvK = (2/ln2)*xv), ONE rcp for 4 values:
//   tanh = 1 - 2/d, d = 2^xvK + 1;  rc = rcp(d0 d1 d2 d3), unwound by muls.
// Clamp xvK <= 30 -> product <= ~2^120 never overflows; tanh(10.4) is within
// 3e-9 of 1 so the clamp is numerically invisible. MUFU: 4 ex2 + 1 rcp.
__device__ __forceinline__ void tanh_quad(float x0, float x1, float x2, float x3,
                                          float& t0, float& t1, float& t2, float& t3) {
    float e0, e1, e2, e3, rc;
    x0 = fminf(x0, 30.f); x1 = fminf(x1, 30.f);
    x2 = fminf(x2, 30.f); x3 = fminf(x3, 30.f);
    asm("ex2.approx.ftz.f32 %0, %1;" : "=f"(e0) : "f"(x0));
    asm("ex2.approx.ftz.f32 %0, %1;" : "=f"(e1) : "f"(x1));
    asm("ex2.approx.ftz.f32 %0, %1;" : "=f"(e2) : "f"(x2));
    asm("ex2.approx.ftz.f32 %0, %1;" : "=f"(e3) : "f"(x3));
    const float d0 = e0 + 1.f, d1 = e1 + 1.f, d2 = e2 + 1.f, d3 = e3 + 1.f;
    const float p01 = d0 * d1, p23 = d2 * d3;
    asm("rcp.approx.ftz.f32 %0, %1;" : "=f"(rc) : "f"(p01 * p23));
    const float rA = rc * p23, rB = rc * p01;   // 1/(d0 d1), 1/(d2 d3)
    t0 = fmaf(-2.f, rA * d1, 1.f);
    t1 = fmaf(-2.f, rA * d0, 1.f);
    t2 = fmaf(-2.f, rB * d3, 1.f);
    t3 = fmaf(-2.f, rB * d2, 1.f);
}

// WARP-PER-SEQUENCE: each warp owns ONE batch sequence end-to-end (32 lanes x
// 32 hidden elems). NO cross-warp exchange, NO per-step __syncthreads -- warps
// are fully autonomous, eliminating the barrier/convoy segment of the per-step
// serial path that bounded R10/R15.
//
// HiPPO bilinear step collapses (A diagonal + rank-1 semiseparable) to ONE
// linear scan over hidden index i:
//   r_{i+1} = alf_i r_i + w_i,  w_i = gam_i h_i + dlt_i u      (r_0 = 0)
//   xv_i    = A1_i h_i + gam_i (c u - (c/2) r_i) ;  h_i = tanh(xv_i)
// Per lane, 32 elems as TWO f32x2-packed chains with layout (i, i+16): the
// sb-chain, r-chain, w and xv run packed at depth 16; the hi chain seeds from
// r16 = A_lo*r0 + cb_lo. Warp scan (time-invariant 'a' ladder precomputed)
// stitches the 32 lane-totals; lane 0 enters with r = 0 (true stream start).
// dlt/A1K constants stream from a lane-indexed smem table shared by all warps.
__global__ void __launch_bounds__(NTHREADS, 1)
ssm_scan_kernel(const float* __restrict__ x,
                const float* __restrict__ C,
                const float* __restrict__ W,
                const float* __restrict__ bias,
                float* __restrict__ out)
{
    __shared__ float      xsv[SEQ][SPB];     // xsv[t][wid]
    __shared__ ulonglong2 tab[EL][32];       // {dlt2, A1K2} per (pair-idx, lane)

    const int tid  = threadIdx.x;
    const int lane = tid & 31;
    const int wid  = tid >> 5;
    const int bidx = blockIdx.x;

    for (int i = tid; i < SPB * SEQ; i += NTHREADS) {
        const int s = i / SEQ, t = i - s * SEQ;
        xsv[t][s] = x[(bidx * SPB + s) * SEQ + t];
    }

    const float KT = 2.885390081777927f;     // 2/ln(2)

    // ---- per-lane constants in double (matches reference fp64 HiPPO).
    //      Pack layout (i, i+16) over this lane's q-range [32*lane, 32*lane+32).
    u64 alf2[EL], gam2[EL], h2[EL], w2[EL], a1k[EL];
    float A_lo = 1.f, A_hi = 1.f;
    u64 mc2K2;
    float cKT;
    {
        const double step = 1.0 / (double)SEQ;
        const double c    = 0.5 * step;
        cKT = (float)c * KT;
        const float m = (float)(-0.5 * c) * KT;
        mc2K2 = pk(m, m);
        #pragma unroll
        for (int i = 0; i < EL; ++i) {
            const double q0 = (double)(lane * 32 + i);
            const double q1 = q0 + 16.0;
            const double P0 = sqrt(1.0 + 2.0 * q0), P1 = sqrt(1.0 + 2.0 * q1);
            const double D0 = 1.0 + c * (1.0 + q0), D1 = 1.0 + c * (1.0 + q1);
            const float a0 = (float)((1.0 - c * q0) / D0);
            const float a1 = (float)((1.0 - c * q1) / D1);
            alf2[i] = pk(a0, a1);
            gam2[i] = pk((float)(2.0 * P0 / D0), (float)(2.0 * P1 / D1));
            a1k[i]  = pk((float)((1.0 - c * (1.0 + q0)) / D0) * KT,
                         (float)((1.0 - c * (1.0 + q1)) / D1) * KT);
            if (wid == 0) {
                ulonglong2 e;
                e.x = pk((float)(step * P0 * P0 / D0), (float)(step * P1 * P1 / D1));
                e.y = a1k[i];
                tab[i][lane] = e;
            }
            h2[i] = 0ull;
            A_lo *= a0; A_hi *= a1;
        }
    }

    // ---- one-time 'a' ladder over lane totals (time-invariant) ----
    float saL[5];
    float sa = A_lo * A_hi;
    #pragma unroll
    for (int k = 0; k < 5; ++k) {
        saL[k] = sa;
        float ra = __shfl_up_sync(0xffffffffu, sa, 1 << k);
        if (lane >= (1 << k)) sa *= ra;
    }
    __syncthreads();                         // xs + tab ready (only pre-epilogue barrier)

    // =========================== main time loop ===========================
    #pragma unroll 1
    for (int t = 0; t < SEQ; ++t) {
        const float u = xsv[t][wid];         // warp-broadcast LDS
        const u64 u2 = pk(u, u);
        const float cuK = cKT * u;
        const u64 cuK2 = pk(cuK, cuK);

        // ---- w and packed serial b-chain (depth 16, two halves in one u64) ----
        u64 sb2 = 0ull;
        #pragma unroll
        for (int i = 0; i < EL; ++i) {
            const ulonglong2 e = tab[i][lane];     // {dlt2, A1K2}
            a1k[i] = e.y;
            w2[i]  = fma2(gam2[i], h2[i], mul2(e.x, u2));
            sb2    = fma2(alf2[i], sb2, w2[i]);
        }
        float cb_lo, cb_hi;
        upk(sb2, cb_lo, cb_hi);
        float tb = fmaf(A_hi, cb_lo, cb_hi);  // lane-total 'b'

        // ---- warp inclusive->exclusive scan on 'b' ('a' ladder precomputed) ----
        float s = tb;
        #pragma unroll
        for (int k = 0; k < 5; ++k) {
            float rb = __shfl_up_sync(0xffffffffu, s, 1 << k);
            if (lane >= (1 << k)) s = fmaf(saL[k], rb, s);
        }
        float eb = __shfl_up_sync(0xffffffffu, s, 1);
        float r0 = (lane == 0) ? 0.f : eb;    // r entering this lane -- NO barrier

        // seed hi chain: r at elem 16 of this lane
        float r16 = fmaf(A_lo, r0, cb_lo);
        u64 r2 = pk(r0, r16);

        // ---- apply: packed r-chain; quad-rcp tanh over (lo_i, hi_i, lo_i+1, hi_i+1) ----
        #pragma unroll
        for (int i = 0; i < EL; i += 2) {
            u64 rhoA = fma2(mc2K2, r2, cuK2);
            u64 xvA  = fma2(gam2[i], rhoA, mul2(a1k[i], h2[i]));
            r2 = fma2(alf2[i], r2, w2[i]);
            u64 rhoB = fma2(mc2K2, r2, cuK2);
            u64 xvB  = fma2(gam2[i + 1], rhoB, mul2(a1k[i + 1], h2[i + 1]));
            r2 = fma2(alf2[i + 1], r2, w2[i + 1]);
            float x0, x1, x2, x3, t0, t1, t2, t3;
            upk(xvA, x0, x1); upk(xvB, x2, x3);
            tanh_quad(x0, x1, x2, x3, t0, t1, t2, t3);
            h2[i]     = pk(t0, t1);
            h2[i + 1] = pk(t2, t3);
        }
    }

    // ---- epilogue (per warp, fully independent): y = C.h ; out = y*W + b ----
    float partial = 0.f;
    #pragma unroll
    for (int i = 0; i < EL; ++i) {
        float hl, hh;
        upk(h2[i], hl, hh);
        partial = fmaf(__ldg(&C[lane * 32 + i]),      hl, partial);
        partial = fmaf(__ldg(&C[lane * 32 + 16 + i]), hh, partial);
    }
    #pragma unroll
    for (int d = 16; d > 0; d >>= 1)
        partial += __shfl_down_sync(0xffffffffu, partial, d);
    if (lane == 0) {
        #pragma unroll
        for (int o = 0; o < 10; ++o)
            out[(bidx * SPB + wid) * 10 + o] = fmaf(partial, W[o], bias[o]);
    }
}

extern "C" void kernel_launch(void* const* d_in, const int* in_sizes, int n_in,
                              void* d_out, int out_size) {
    const float* x    = (const float*)d_in[0];   // (512, 784, 1)
    const float* C    = (const float*)d_in[1];   // (1, 1024)
    const float* W    = (const float*)d_in[2];   // (1, 10)
    const float* bias = (const float*)d_in[3];   // (10,)
    float* out        = (float*)d_out;           // (512, 10)
    ssm_scan_kernel<<<BATCH / SPB, NTHREADS>>>(x, C, W, bias, out);
}